// round 2
// baseline (speedup 1.0000x reference)
#include <cuda_runtime.h>
#include <cstdint>

#define B_  512
#define T_  256
#define C_  256
#define H_  64

// Scratch for Q, K, V projections: 3 x 32 MB (allocation-free: __device__ globals).
__device__ float g_Q[B_ * T_ * H_];
__device__ float g_K[B_ * T_ * H_];
__device__ float g_V[B_ * T_ * H_];

// Round-to-nearest fp32 -> tf32 (bits kept in a 32-bit reg). Unbiased rounding is
// load-bearing for precision: truncation would add a correlated ~7e-4 bias.
__device__ __forceinline__ unsigned f2tf(float x) {
    unsigned r;
    asm("cvt.rna.tf32.f32 %0, %1;" : "=r"(r) : "f"(x));
    return r;
}

// m16n8k8 tf32 mma: D += A*B. A: 4 regs, B: 2 regs, C/D: 4 fp32.
__device__ __forceinline__ void mma8(float* d, const unsigned* a, const unsigned* b) {
    asm volatile(
        "mma.sync.aligned.m16n8k8.row.col.f32.tf32.tf32.f32 "
        "{%0,%1,%2,%3},{%4,%5,%6,%7},{%8,%9},{%0,%1,%2,%3};"
        : "+f"(d[0]), "+f"(d[1]), "+f"(d[2]), "+f"(d[3])
        : "r"(a[0]), "r"(a[1]), "r"(a[2]), "r"(a[3]), "r"(b[0]), "r"(b[1]));
}

// ---------------------------------------------------------------------------
// Kernel 1: QKV projection.  out[g] = x @ W[g],  g in {q,k,v}
// GEMM M=131072, N=64 (per g), K=256. CTA tile 128x64, BK=32, 8 warps (4x2).
// grid = (3, nblocks): the three g-variants of one m-block are adjacent in
// linear block order -> the shared x tile is read from DRAM once, hit in L2
// twice (saves ~250 MB of DRAM traffic vs. (nblocks, 3) ordering).
// ---------------------------------------------------------------------------
__global__ __launch_bounds__(256) void qkv_kernel(
    const float* __restrict__ x,
    const float* __restrict__ Wq,
    const float* __restrict__ Wk,
    const float* __restrict__ Wv)
{
    __shared__ unsigned As[128][36];  // pad 36: banks (4r+c)%32 conflict-free
    __shared__ unsigned Bs[32][72];   // pad 72: banks (8k+n)%32 conflict-free

    const int tid  = threadIdx.x;
    const int lane = tid & 31;
    const int warp = tid >> 5;
    const int wm   = warp >> 1;   // 0..3
    const int wn   = warp & 1;    // 0..1
    const int mblk = blockIdx.y;
    const int which = blockIdx.x;

    const float* W    = (which == 0) ? Wq : (which == 1 ? Wk : Wv);
    float*       outp = (which == 0) ? g_Q : (which == 1 ? g_K : g_V);

    float acc[2][4][4];
    #pragma unroll
    for (int i = 0; i < 2; i++)
        #pragma unroll
        for (int j = 0; j < 4; j++)
            #pragma unroll
            for (int c = 0; c < 4; c++) acc[i][j][c] = 0.f;

    const long rowbase = (long)mblk * 128;

    for (int k0 = 0; k0 < 256; k0 += 32) {
        // Load A tile 128x32 (4 float4 per thread, fully coalesced)
        #pragma unroll
        for (int i = 0; i < 4; i++) {
            int idx = tid + i * 256;            // 0..1023
            int r = idx >> 3, c4 = idx & 7;     // 8 float4 per row
            float4 v = *(const float4*)(x + (rowbase + r) * 256 + k0 + c4 * 4);
            As[r][c4 * 4 + 0] = f2tf(v.x);
            As[r][c4 * 4 + 1] = f2tf(v.y);
            As[r][c4 * 4 + 2] = f2tf(v.z);
            As[r][c4 * 4 + 3] = f2tf(v.w);
        }
        // Load B tile 32x64 (2 float4 per thread)
        #pragma unroll
        for (int i = 0; i < 2; i++) {
            int idx = tid + i * 256;            // 0..511
            int r = idx >> 4, c4 = idx & 15;    // 16 float4 per row
            float4 v = *(const float4*)(W + (k0 + r) * 64 + c4 * 4);
            Bs[r][c4 * 4 + 0] = f2tf(v.x);
            Bs[r][c4 * 4 + 1] = f2tf(v.y);
            Bs[r][c4 * 4 + 2] = f2tf(v.z);
            Bs[r][c4 * 4 + 3] = f2tf(v.w);
        }
        __syncthreads();

        #pragma unroll
        for (int kk = 0; kk < 4; kk++) {
            unsigned a[2][4], b[4][2];
            const int ar = wm * 32 + (lane >> 2);
            const int ac = kk * 8 + (lane & 3);
            #pragma unroll
            for (int mt = 0; mt < 2; mt++) {
                a[mt][0] = As[ar + mt * 16][ac];
                a[mt][1] = As[ar + mt * 16 + 8][ac];
                a[mt][2] = As[ar + mt * 16][ac + 4];
                a[mt][3] = As[ar + mt * 16 + 8][ac + 4];
            }
            const int bk = kk * 8 + (lane & 3);
            #pragma unroll
            for (int nt = 0; nt < 4; nt++) {
                int bn = wn * 32 + nt * 8 + (lane >> 2);
                b[nt][0] = Bs[bk][bn];
                b[nt][1] = Bs[bk + 4][bn];
            }
            #pragma unroll
            for (int mt = 0; mt < 2; mt++)
                #pragma unroll
                for (int nt = 0; nt < 4; nt++)
                    mma8(acc[mt][nt], a[mt], b[nt]);
        }
        __syncthreads();
    }

    // Store: c0,c1 contiguous -> float2, fully coalesced per quad.
    #pragma unroll
    for (int mt = 0; mt < 2; mt++) {
        long r0 = rowbase + wm * 32 + mt * 16 + (lane >> 2);
        #pragma unroll
        for (int nt = 0; nt < 4; nt++) {
            int cc = wn * 32 + nt * 8 + 2 * (lane & 3);
            *(float2*)(outp + r0 * 64 + cc)       = make_float2(acc[mt][nt][0], acc[mt][nt][1]);
            *(float2*)(outp + (r0 + 8) * 64 + cc) = make_float2(acc[mt][nt][2], acc[mt][nt][3]);
        }
    }
}

// ---------------------------------------------------------------------------
// Kernel 2: fused causal attention, one CTA per batch.
// K,V resident in smem (tf32), Q frags in registers (warp owns 32 query rows).
// Logits are O(1), so no max-subtraction needed: accumulate numerator+denominator.
// s-blocks of 32; P round-trips through per-warp smem to become mma A-frags.
// ---------------------------------------------------------------------------
#define SMEM_K_WORDS (256 * 68)
#define SMEM_V_WORDS (256 * 72)
#define SMEM_P_WORDS (32 * 36)
#define ATTN_SMEM_BYTES ((SMEM_K_WORDS + SMEM_V_WORDS + 8 * SMEM_P_WORDS) * 4)

__global__ __launch_bounds__(256) void attn_kernel(float* __restrict__ out)
{
    extern __shared__ unsigned sm[];
    unsigned* sK = sm;                              // [256][68]
    unsigned* sV = sm + SMEM_K_WORDS;               // [256][72]
    const int tid  = threadIdx.x;
    const int lane = tid & 31;
    const int warp = tid >> 5;
    unsigned* sP = sm + SMEM_K_WORDS + SMEM_V_WORDS + warp * SMEM_P_WORDS;  // [32][36]

    const int b = blockIdx.x;
    const float* Qg = g_Q + (long)b * T_ * H_;
    const float* Kg = g_K + (long)b * T_ * H_;
    const float* Vg = g_V + (long)b * T_ * H_;

    // Stage K and V (tf32-rounded) into smem. 16 rows' worth of float4 per thread.
    #pragma unroll
    for (int i = 0; i < 16; i++) {
        int idx = tid + i * 256;          // 0..4095
        int r = idx >> 4, c4 = idx & 15;  // 16 float4 per 64-float row
        float4 kv = *(const float4*)(Kg + r * 64 + c4 * 4);
        sK[r * 68 + c4 * 4 + 0] = f2tf(kv.x);
        sK[r * 68 + c4 * 4 + 1] = f2tf(kv.y);
        sK[r * 68 + c4 * 4 + 2] = f2tf(kv.z);
        sK[r * 68 + c4 * 4 + 3] = f2tf(kv.w);
        float4 vv = *(const float4*)(Vg + r * 64 + c4 * 4);
        sV[r * 72 + c4 * 4 + 0] = f2tf(vv.x);
        sV[r * 72 + c4 * 4 + 1] = f2tf(vv.y);
        sV[r * 72 + c4 * 4 + 2] = f2tf(vv.z);
        sV[r * 72 + c4 * 4 + 3] = f2tf(vv.w);
    }
    __syncthreads();

    const int t0 = warp * 32;  // this warp's query rows [t0, t0+32)

    // Q fragments for all 8 k-steps (head dim 64), kept in registers.
    unsigned aq[2][8][4];
    #pragma unroll
    for (int mt = 0; mt < 2; mt++) {
        const int r = t0 + mt * 16 + (lane >> 2);
        #pragma unroll
        for (int kt = 0; kt < 8; kt++) {
            const int c = kt * 8 + (lane & 3);
            aq[mt][kt][0] = f2tf(Qg[r * 64 + c]);
            aq[mt][kt][1] = f2tf(Qg[(r + 8) * 64 + c]);
            aq[mt][kt][2] = f2tf(Qg[r * 64 + c + 4]);
            aq[mt][kt][3] = f2tf(Qg[(r + 8) * 64 + c + 4]);
        }
    }

    float o[2][8][4];
    #pragma unroll
    for (int mt = 0; mt < 2; mt++)
        #pragma unroll
        for (int nt = 0; nt < 8; nt++)
            #pragma unroll
            for (int c = 0; c < 4; c++) o[mt][nt][c] = 0.f;
    float rs[2][2] = {{0.f, 0.f}, {0.f, 0.f}};  // per (m-tile, row-half) denominator partials

    const int nblk = warp + 1;  // causal: s-blocks of 32 with s <= t
    for (int sb = 0; sb < nblk; sb++) {
        const int s0 = sb * 32;

        // --- S = Q @ K^T for this 32x32 block ---
        float sacc[2][4][4];
        #pragma unroll
        for (int mt = 0; mt < 2; mt++)
            #pragma unroll
            for (int nt = 0; nt < 4; nt++)
                #pragma unroll
                for (int c = 0; c < 4; c++) sacc[mt][nt][c] = 0.f;

        #pragma unroll
        for (int kt = 0; kt < 8; kt++) {
            unsigned bk[4][2];
            const int hh = kt * 8 + (lane & 3);
            #pragma unroll
            for (int nt = 0; nt < 4; nt++) {
                int ss = s0 + nt * 8 + (lane >> 2);
                bk[nt][0] = sK[ss * 68 + hh];
                bk[nt][1] = sK[ss * 68 + hh + 4];
            }
            #pragma unroll
            for (int mt = 0; mt < 2; mt++)
                #pragma unroll
                for (int nt = 0; nt < 4; nt++)
                    mma8(sacc[mt][nt], aq[mt][kt], bk[nt]);
        }

        // --- mask + exp + denominator accumulate + stash P to smem ---
        #pragma unroll
        for (int mt = 0; mt < 2; mt++) {
            #pragma unroll
            for (int ci2 = 0; ci2 < 2; ci2++) {  // row half (c0c1 vs c2c3)
                const int rl = mt * 16 + (lane >> 2) + ci2 * 8;
                const int t  = t0 + rl;
                float rsum = 0.f;
                #pragma unroll
                for (int nt = 0; nt < 4; nt++) {
                    #pragma unroll
                    for (int e = 0; e < 2; e++) {
                        const int s  = s0 + nt * 8 + 2 * (lane & 3) + e;
                        const int ci = ci2 * 2 + e;
                        float p = (s <= t) ? __expf(sacc[mt][nt][ci] * 0.0625f) : 0.f;
                        rsum += p;
                        sP[rl * 36 + nt * 8 + 2 * (lane & 3) + e] = f2tf(p);
                    }
                }
                rs[mt][ci2] += rsum;
            }
        }
        __syncwarp();

        // --- O += P @ V for this block: A = P (32x32), B = V (32x64) ---
        #pragma unroll
        for (int kt = 0; kt < 4; kt++) {
            unsigned ap[2][4];
            const int pc = kt * 8 + (lane & 3);
            #pragma unroll
            for (int mt = 0; mt < 2; mt++) {
                const int rl = mt * 16 + (lane >> 2);
                ap[mt][0] = sP[rl * 36 + pc];
                ap[mt][1] = sP[(rl + 8) * 36 + pc];
                ap[mt][2] = sP[rl * 36 + pc + 4];
                ap[mt][3] = sP[(rl + 8) * 36 + pc + 4];
            }
            unsigned bv[8][2];
            const int sv = s0 + kt * 8 + (lane & 3);
            #pragma unroll
            for (int nt = 0; nt < 8; nt++) {
                const int hh = nt * 8 + (lane >> 2);
                bv[nt][0] = sV[sv * 72 + hh];
                bv[nt][1] = sV[(sv + 4) * 72 + hh];
            }
            #pragma unroll
            for (int mt = 0; mt < 2; mt++)
                #pragma unroll
                for (int nt = 0; nt < 8; nt++)
                    mma8(o[mt][nt], ap[mt], bv[nt]);
        }
        __syncwarp();  // sP reused next block
    }

    // Reduce denominators across the 4 lanes of each row-quad.
    #pragma unroll
    for (int mt = 0; mt < 2; mt++)
        #pragma unroll
        for (int h2 = 0; h2 < 2; h2++) {
            float r = rs[mt][h2];
            r += __shfl_xor_sync(0xffffffffu, r, 1);
            r += __shfl_xor_sync(0xffffffffu, r, 2);
            rs[mt][h2] = 1.f / r;
        }

    // Write output (float2, coalesced per quad).
    float* ob = out + (long)b * T_ * H_;
    #pragma unroll
    for (int mt = 0; mt < 2; mt++) {
        const int r = t0 + mt * 16 + (lane >> 2);
        #pragma unroll
        for (int nt = 0; nt < 8; nt++) {
            const int cc = nt * 8 + 2 * (lane & 3);
            *(float2*)(ob + r * 64 + cc) =
                make_float2(o[mt][nt][0] * rs[mt][0], o[mt][nt][1] * rs[mt][0]);
            *(float2*)(ob + (r + 8) * 64 + cc) =
                make_float2(o[mt][nt][2] * rs[mt][1], o[mt][nt][3] * rs[mt][1]);
        }
    }
}

// ---------------------------------------------------------------------------
extern "C" void kernel_launch(void* const* d_in, const int* in_sizes, int n_in,
                              void* d_out, int out_size)
{
    const float* x  = (const float*)d_in[0];
    const float* Wq = (const float*)d_in[1];
    const float* Wk = (const float*)d_in[2];
    const float* Wv = (const float*)d_in[3];
    float* out = (float*)d_out;

    (void)in_sizes; (void)n_in; (void)out_size;

    // Idempotent; needed for 176 KB dynamic smem.
    cudaFuncSetAttribute(attn_kernel, cudaFuncAttributeMaxDynamicSharedMemorySize,
                         ATTN_SMEM_BYTES);

    qkv_kernel<<<dim3(3, (B_ * T_) / 128), 256>>>(x, Wq, Wk, Wv);
    attn_kernel<<<B_, 256, ATTN_SMEM_BYTES>>>(out);
}

// round 3
// speedup vs baseline: 1.1137x; 1.1137x over previous
#include <cuda_runtime.h>
#include <cstdint>

#define B_  512
#define T_  256
#define C_  256
#define H_  64

// Scratch for Q, K, V projections (allocation-free: __device__ globals).
__device__ float g_Q[B_ * T_ * H_];
__device__ float g_K[B_ * T_ * H_];
__device__ float g_V[B_ * T_ * H_];

// Round-to-nearest fp32 -> tf32 bits. Unbiased rounding is load-bearing.
__device__ __forceinline__ unsigned f2tf(float x) {
    unsigned r;
    asm("cvt.rna.tf32.f32 %0, %1;" : "=r"(r) : "f"(x));
    return r;
}

// m16n8k8 tf32 mma: D += A*B. A: 4 regs, B: 2 regs, C/D: 4 fp32.
__device__ __forceinline__ void mma8(float* d, const unsigned* a, const unsigned* b) {
    asm volatile(
        "mma.sync.aligned.m16n8k8.row.col.f32.tf32.tf32.f32 "
        "{%0,%1,%2,%3},{%4,%5,%6,%7},{%8,%9},{%0,%1,%2,%3};"
        : "+f"(d[0]), "+f"(d[1]), "+f"(d[2]), "+f"(d[3])
        : "r"(a[0]), "r"(a[1]), "r"(a[2]), "r"(a[3]), "r"(b[0]), "r"(b[1]));
}

// ---------------------------------------------------------------------------
// Kernel 1: QKV projection.  out[g] = x @ W[g].
// M=131072, N=64 per g, K=256. CTA tile 128x64, BK=32, 8 warps (4x2).
// Software pipeline: prefetch next K-slab into registers, cvt at STS into a
// double-buffered smem tile, ONE __syncthreads per K-step (overwrite of
// buf[k&1] only happens at iter k+2, after iter k+1's barrier which program-
// order-follows every warp's compute(k)).
// grid = (3, nblocks): the 3 g-variants of an m-block are adjacent -> x tile
// hits L2 twice instead of re-reading DRAM.
// ---------------------------------------------------------------------------
#define QKV_SMEM_WORDS (2 * 128 * 36 + 2 * 32 * 72)
#define QKV_SMEM_BYTES (QKV_SMEM_WORDS * 4)

__global__ __launch_bounds__(256, 2) void qkv_kernel(
    const float* __restrict__ x,
    const float* __restrict__ Wq,
    const float* __restrict__ Wk,
    const float* __restrict__ Wv)
{
    extern __shared__ unsigned qsm[];
    // As[2][128][36] then Bs[2][32][72]
    unsigned* AsBase = qsm;
    unsigned* BsBase = qsm + 2 * 128 * 36;

    const int tid  = threadIdx.x;
    const int lane = tid & 31;
    const int warp = tid >> 5;
    const int wm   = warp >> 1;   // 0..3
    const int wn   = warp & 1;    // 0..1
    const int mblk = blockIdx.y;
    const int which = blockIdx.x;

    const float* W    = (which == 0) ? Wq : (which == 1 ? Wk : Wv);
    float*       outp = (which == 0) ? g_Q : (which == 1 ? g_K : g_V);

    float acc[2][4][4];
    #pragma unroll
    for (int i = 0; i < 2; i++)
        #pragma unroll
        for (int j = 0; j < 4; j++)
            #pragma unroll
            for (int c = 0; c < 4; c++) acc[i][j][c] = 0.f;

    const long rowbase = (long)mblk * 128;

    // Per-thread staging coords (fixed across iterations).
    const int ar_ = tid >> 3, ac4_ = tid & 7;    // A: 128 rows x 8 float4
    const int br_ = tid >> 4, bc4_ = tid & 15;   // B: 32 rows x 16 float4

    float4 ra[4], rb[2];
    // Prefetch k0 = 0.
    #pragma unroll
    for (int i = 0; i < 4; i++)
        ra[i] = *(const float4*)(x + (rowbase + ar_ + i * 32) * 256 + ac4_ * 4);
    #pragma unroll
    for (int i = 0; i < 2; i++)
        rb[i] = *(const float4*)(W + (br_ + i * 16) * 64 + bc4_ * 4);

    for (int k0 = 0; k0 < 8; k0++) {
        const int buf = k0 & 1;
        unsigned* As = AsBase + buf * 128 * 36;   // [128][36]
        unsigned* Bs = BsBase + buf * 32 * 72;    // [32][72]

        // STS with rna cvt.
        #pragma unroll
        for (int i = 0; i < 4; i++) {
            unsigned* p = As + (ar_ + i * 32) * 36 + ac4_ * 4;
            p[0] = f2tf(ra[i].x); p[1] = f2tf(ra[i].y);
            p[2] = f2tf(ra[i].z); p[3] = f2tf(ra[i].w);
        }
        #pragma unroll
        for (int i = 0; i < 2; i++) {
            unsigned* p = Bs + (br_ + i * 16) * 72 + bc4_ * 4;
            p[0] = f2tf(rb[i].x); p[1] = f2tf(rb[i].y);
            p[2] = f2tf(rb[i].z); p[3] = f2tf(rb[i].w);
        }

        // Prefetch next slab (latency overlapped with compute below).
        if (k0 < 7) {
            const int kn = (k0 + 1) * 32;
            #pragma unroll
            for (int i = 0; i < 4; i++)
                ra[i] = *(const float4*)(x + (rowbase + ar_ + i * 32) * 256 + kn + ac4_ * 4);
            #pragma unroll
            for (int i = 0; i < 2; i++)
                rb[i] = *(const float4*)(W + (kn + br_ + i * 16) * 64 + bc4_ * 4);
        }
        __syncthreads();

        #pragma unroll
        for (int kk = 0; kk < 4; kk++) {
            unsigned a[2][4], b[4][2];
            const int ar = wm * 32 + (lane >> 2);
            const int ac = kk * 8 + (lane & 3);
            #pragma unroll
            for (int mt = 0; mt < 2; mt++) {
                a[mt][0] = As[(ar + mt * 16) * 36 + ac];
                a[mt][1] = As[(ar + mt * 16 + 8) * 36 + ac];
                a[mt][2] = As[(ar + mt * 16) * 36 + ac + 4];
                a[mt][3] = As[(ar + mt * 16 + 8) * 36 + ac + 4];
            }
            const int bk = kk * 8 + (lane & 3);
            #pragma unroll
            for (int nt = 0; nt < 4; nt++) {
                const int bn = wn * 32 + nt * 8 + (lane >> 2);
                b[nt][0] = Bs[bk * 72 + bn];
                b[nt][1] = Bs[(bk + 4) * 72 + bn];
            }
            #pragma unroll
            for (int mt = 0; mt < 2; mt++)
                #pragma unroll
                for (int nt = 0; nt < 4; nt++)
                    mma8(acc[mt][nt], a[mt], b[nt]);
        }
    }

    // Store (c0,c1 contiguous -> float2, coalesced per quad).
    #pragma unroll
    for (int mt = 0; mt < 2; mt++) {
        long r0 = rowbase + wm * 32 + mt * 16 + (lane >> 2);
        #pragma unroll
        for (int nt = 0; nt < 4; nt++) {
            int cc = wn * 32 + nt * 8 + 2 * (lane & 3);
            *(float2*)(outp + r0 * 64 + cc)       = make_float2(acc[mt][nt][0], acc[mt][nt][1]);
            *(float2*)(outp + (r0 + 8) * 64 + cc) = make_float2(acc[mt][nt][2], acc[mt][nt][3]);
        }
    }
}

// ---------------------------------------------------------------------------
// Kernel 2: fused causal attention, one CTA per batch, BALANCED causal work:
// 16 m-tiles of 16 query rows; warp w processes tiles {w, 15-w} sequentially.
// Tile m needs m/2+1 s-blocks of 32 -> every warp does exactly 9 block-units
// (previous scheme: warp 7 did 16 while warp 0 did 2).
// K,V resident in smem (tf32). Logits are O(1) -> plain num/denom softmax.
// ---------------------------------------------------------------------------
#define SMEM_K_WORDS (256 * 68)
#define SMEM_V_WORDS (256 * 72)
#define SMEM_P_WORDS (16 * 36)
#define ATTN_SMEM_BYTES ((SMEM_K_WORDS + SMEM_V_WORDS + 8 * SMEM_P_WORDS) * 4)

__global__ __launch_bounds__(256, 1) void attn_kernel(float* __restrict__ out)
{
    extern __shared__ unsigned sm[];
    unsigned* sK = sm;                              // [256][68]
    unsigned* sV = sm + SMEM_K_WORDS;               // [256][72]
    const int tid  = threadIdx.x;
    const int lane = tid & 31;
    const int warp = tid >> 5;
    unsigned* sP = sm + SMEM_K_WORDS + SMEM_V_WORDS + warp * SMEM_P_WORDS;  // [16][36]

    const int b = blockIdx.x;
    const float* Qg = g_Q + (long)b * T_ * H_;
    const float* Kg = g_K + (long)b * T_ * H_;
    const float* Vg = g_V + (long)b * T_ * H_;
    float* ob = out + (long)b * T_ * H_;

    // Stage K and V (tf32-rounded) into smem.
    #pragma unroll
    for (int i = 0; i < 16; i++) {
        int idx = tid + i * 256;
        int r = idx >> 4, c4 = idx & 15;
        float4 kv = *(const float4*)(Kg + r * 64 + c4 * 4);
        sK[r * 68 + c4 * 4 + 0] = f2tf(kv.x);
        sK[r * 68 + c4 * 4 + 1] = f2tf(kv.y);
        sK[r * 68 + c4 * 4 + 2] = f2tf(kv.z);
        sK[r * 68 + c4 * 4 + 3] = f2tf(kv.w);
        float4 vv = *(const float4*)(Vg + r * 64 + c4 * 4);
        sV[r * 72 + c4 * 4 + 0] = f2tf(vv.x);
        sV[r * 72 + c4 * 4 + 1] = f2tf(vv.y);
        sV[r * 72 + c4 * 4 + 2] = f2tf(vv.z);
        sV[r * 72 + c4 * 4 + 3] = f2tf(vv.w);
    }
    __syncthreads();

    #pragma unroll 1
    for (int half = 0; half < 2; half++) {
        const int m  = (half == 0) ? warp : 15 - warp;
        const int t0 = m * 16;

        // Q fragments for this 16-row tile (8 k-steps over head dim 64).
        unsigned aq[8][4];
        {
            const int r = t0 + (lane >> 2);
            #pragma unroll
            for (int kt = 0; kt < 8; kt++) {
                const int c = kt * 8 + (lane & 3);
                aq[kt][0] = f2tf(Qg[r * 64 + c]);
                aq[kt][1] = f2tf(Qg[(r + 8) * 64 + c]);
                aq[kt][2] = f2tf(Qg[r * 64 + c + 4]);
                aq[kt][3] = f2tf(Qg[(r + 8) * 64 + c + 4]);
            }
        }

        float o[8][4];
        #pragma unroll
        for (int nt = 0; nt < 8; nt++)
            #pragma unroll
            for (int c = 0; c < 4; c++) o[nt][c] = 0.f;
        float rs[2] = {0.f, 0.f};

        const int nb = m / 2 + 1;
        for (int sb = 0; sb < nb; sb++) {
            const int s0 = sb * 32;

            // --- S = Q @ K^T (16x32 block) ---
            float sacc[4][4];
            #pragma unroll
            for (int nt = 0; nt < 4; nt++)
                #pragma unroll
                for (int c = 0; c < 4; c++) sacc[nt][c] = 0.f;

            #pragma unroll
            for (int kt = 0; kt < 8; kt++) {
                unsigned bk[4][2];
                const int hh = kt * 8 + (lane & 3);
                #pragma unroll
                for (int nt = 0; nt < 4; nt++) {
                    int ss = s0 + nt * 8 + (lane >> 2);
                    bk[nt][0] = sK[ss * 68 + hh];
                    bk[nt][1] = sK[ss * 68 + hh + 4];
                }
                #pragma unroll
                for (int nt = 0; nt < 4; nt++)
                    mma8(sacc[nt], aq[kt], bk[nt]);
            }

            // --- mask + exp + denominator + stash P ---
            #pragma unroll
            for (int ci2 = 0; ci2 < 2; ci2++) {
                const int rl = (lane >> 2) + ci2 * 8;
                const int t  = t0 + rl;
                float rsum = 0.f;
                #pragma unroll
                for (int nt = 0; nt < 4; nt++) {
                    #pragma unroll
                    for (int e = 0; e < 2; e++) {
                        const int s  = s0 + nt * 8 + 2 * (lane & 3) + e;
                        const int ci = ci2 * 2 + e;
                        float p = (s <= t) ? __expf(sacc[nt][ci] * 0.0625f) : 0.f;
                        rsum += p;
                        sP[rl * 36 + nt * 8 + 2 * (lane & 3) + e] = f2tf(p);
                    }
                }
                rs[ci2] += rsum;
            }
            __syncwarp();

            // --- O += P @ V (A = P 16x32, B = V 32x64) ---
            #pragma unroll
            for (int kt = 0; kt < 4; kt++) {
                unsigned ap[4];
                const int pc = kt * 8 + (lane & 3);
                const int rl = lane >> 2;
                ap[0] = sP[rl * 36 + pc];
                ap[1] = sP[(rl + 8) * 36 + pc];
                ap[2] = sP[rl * 36 + pc + 4];
                ap[3] = sP[(rl + 8) * 36 + pc + 4];
                unsigned bv[8][2];
                const int sv = s0 + kt * 8 + (lane & 3);
                #pragma unroll
                for (int nt = 0; nt < 8; nt++) {
                    const int hh = nt * 8 + (lane >> 2);
                    bv[nt][0] = sV[sv * 72 + hh];
                    bv[nt][1] = sV[(sv + 4) * 72 + hh];
                }
                #pragma unroll
                for (int nt = 0; nt < 8; nt++)
                    mma8(o[nt], ap, bv[nt]);
            }
            __syncwarp();  // sP reused next block
        }

        // Denominators: reduce across the 4 lanes of each row-quad.
        #pragma unroll
        for (int h2 = 0; h2 < 2; h2++) {
            float r = rs[h2];
            r += __shfl_xor_sync(0xffffffffu, r, 1);
            r += __shfl_xor_sync(0xffffffffu, r, 2);
            rs[h2] = 1.f / r;
        }

        // Write this tile's output (float2, coalesced per quad).
        const int r = t0 + (lane >> 2);
        #pragma unroll
        for (int nt = 0; nt < 8; nt++) {
            const int cc = nt * 8 + 2 * (lane & 3);
            *(float2*)(ob + r * 64 + cc) =
                make_float2(o[nt][0] * rs[0], o[nt][1] * rs[0]);
            *(float2*)(ob + (r + 8) * 64 + cc) =
                make_float2(o[nt][2] * rs[1], o[nt][3] * rs[1]);
        }
    }
}

// ---------------------------------------------------------------------------
extern "C" void kernel_launch(void* const* d_in, const int* in_sizes, int n_in,
                              void* d_out, int out_size)
{
    const float* x  = (const float*)d_in[0];
    const float* Wq = (const float*)d_in[1];
    const float* Wk = (const float*)d_in[2];
    const float* Wv = (const float*)d_in[3];
    float* out = (float*)d_out;

    (void)in_sizes; (void)n_in; (void)out_size;

    // Idempotent; needed for >48 KB dynamic smem.
    cudaFuncSetAttribute(qkv_kernel, cudaFuncAttributeMaxDynamicSharedMemorySize,
                         QKV_SMEM_BYTES);
    cudaFuncSetAttribute(attn_kernel, cudaFuncAttributeMaxDynamicSharedMemorySize,
                         ATTN_SMEM_BYTES);

    qkv_kernel<<<dim3(3, (B_ * T_) / 128), 256, QKV_SMEM_BYTES>>>(x, Wq, Wk, Wv);
    attn_kernel<<<B_, 256, ATTN_SMEM_BYTES>>>(out);
}

// round 4
// speedup vs baseline: 1.2919x; 1.1599x over previous
#include <cuda_runtime.h>
#include <cstdint>

#define B_  512
#define T_  256
#define C_  256
#define H_  64

// Scratch for Q, K, V projections (allocation-free: __device__ globals).
__device__ float g_Q[B_ * T_ * H_];
__device__ float g_K[B_ * T_ * H_];
__device__ float g_V[B_ * T_ * H_];

// fp32 -> tf32 bits, round-to-nearest (unbiased; load-bearing for precision).
__device__ __forceinline__ unsigned f2tf(float x) {
    unsigned r;
    asm("cvt.rna.tf32.f32 %0, %1;" : "=r"(r) : "f"(x));
    return r;
}
// pack two fp32 -> bf16x2 word {lo, hi} (lo = first/even-k element).
__device__ __forceinline__ unsigned pkbf(float lo, float hi) {
    unsigned r;
    asm("cvt.rn.bf16x2.f32 %0, %1, %2;" : "=r"(r) : "f"(hi), "f"(lo));
    return r;
}

// m16n8k8 tf32 mma: D += A*B.
__device__ __forceinline__ void mma8(float* d, const unsigned* a, const unsigned* b) {
    asm volatile(
        "mma.sync.aligned.m16n8k8.row.col.f32.tf32.tf32.f32 "
        "{%0,%1,%2,%3},{%4,%5,%6,%7},{%8,%9},{%0,%1,%2,%3};"
        : "+f"(d[0]), "+f"(d[1]), "+f"(d[2]), "+f"(d[3])
        : "r"(a[0]), "r"(a[1]), "r"(a[2]), "r"(a[3]), "r"(b[0]), "r"(b[1]));
}
// m16n8k16 bf16 mma: D += A*B.
__device__ __forceinline__ void mma16(float* d, const unsigned* a, const unsigned* b) {
    asm volatile(
        "mma.sync.aligned.m16n8k16.row.col.f32.bf16.bf16.f32 "
        "{%0,%1,%2,%3},{%4,%5,%6,%7},{%8,%9},{%0,%1,%2,%3};"
        : "+f"(d[0]), "+f"(d[1]), "+f"(d[2]), "+f"(d[3])
        : "r"(a[0]), "r"(a[1]), "r"(a[2]), "r"(a[3]), "r"(b[0]), "r"(b[1]));
}

// ---------------------------------------------------------------------------
// Kernel 1: QKV projection, mixed precision.
//   which 0/1 (Q,K): bf16 m16n8k16 path (halved mma/LDS instruction stream;
//                    logit error contribution ~2.6e-4, safe).
//   which 2   (V)  : tf32 path (V errors propagate directly to output).
// CTA tile 128x64, BK=32, 8 warps (4x2), double-buffered smem, 1 barrier/step.
// grid=(3, nblocks): g-variants of an m-block adjacent -> x tile reused in L2.
// ---------------------------------------------------------------------------
// tf32 path layout (larger): As[2][128][36] + Bs[2][32][72] words.
#define QKV_SMEM_WORDS (2 * 128 * 36 + 2 * 32 * 72)
#define QKV_SMEM_BYTES (QKV_SMEM_WORDS * 4)

__global__ __launch_bounds__(256, 2) void qkv_kernel(
    const float* __restrict__ x,
    const float* __restrict__ Wq,
    const float* __restrict__ Wk,
    const float* __restrict__ Wv)
{
    extern __shared__ unsigned qsm[];

    const int tid  = threadIdx.x;
    const int lane = tid & 31;
    const int warp = tid >> 5;
    const int wm   = warp >> 1;
    const int wn   = warp & 1;
    const int mblk = blockIdx.y;
    const int which = blockIdx.x;
    const long rowbase = (long)mblk * 128;

    float acc[2][4][4];
    #pragma unroll
    for (int i = 0; i < 2; i++)
        #pragma unroll
        for (int j = 0; j < 4; j++)
            #pragma unroll
            for (int c = 0; c < 4; c++) acc[i][j][c] = 0.f;

    if (which < 2) {
        // ================= bf16 path (Q, K) =================
        const float* W    = (which == 0) ? Wq : Wk;
        float*       outp = (which == 0) ? g_Q : g_K;
        unsigned* Aw = qsm;                 // [2][128][20] bf16x2 words
        unsigned* Bw = qsm + 2 * 128 * 20;  // [2][64][20]  bf16x2 words (n-major)

        const int ar_ = tid >> 3, ac4_ = tid & 7;   // A: 128 rows x 8 float4
        const int n_  = tid & 63, g_   = tid >> 6;  // B: 64 n x 4 kw-groups

        float4 ra[4];
        float rbl[4], rbh[4];
        #pragma unroll
        for (int i = 0; i < 4; i++)
            ra[i] = *(const float4*)(x + (rowbase + ar_ + i * 32) * 256 + ac4_ * 4);
        #pragma unroll
        for (int i = 0; i < 4; i++) {
            int k = 2 * (g_ * 4 + i);
            rbl[i] = W[k * 64 + n_];
            rbh[i] = W[(k + 1) * 64 + n_];
        }

        for (int k0 = 0; k0 < 8; k0++) {
            const int buf = k0 & 1;
            unsigned* As = Aw + buf * 128 * 20;
            unsigned* Bs = Bw + buf * 64 * 20;

            #pragma unroll
            for (int i = 0; i < 4; i++) {
                unsigned* p = As + (ar_ + i * 32) * 20 + ac4_ * 2;
                p[0] = pkbf(ra[i].x, ra[i].y);
                p[1] = pkbf(ra[i].z, ra[i].w);
            }
            #pragma unroll
            for (int i = 0; i < 4; i++)
                Bs[n_ * 20 + g_ * 4 + i] = pkbf(rbl[i], rbh[i]);

            if (k0 < 7) {
                const int kn = (k0 + 1) * 32;
                #pragma unroll
                for (int i = 0; i < 4; i++)
                    ra[i] = *(const float4*)(x + (rowbase + ar_ + i * 32) * 256 + kn + ac4_ * 4);
                #pragma unroll
                for (int i = 0; i < 4; i++) {
                    int k = kn + 2 * (g_ * 4 + i);
                    rbl[i] = W[k * 64 + n_];
                    rbh[i] = W[(k + 1) * 64 + n_];
                }
            }
            __syncthreads();

            #pragma unroll
            for (int s = 0; s < 2; s++) {  // two k16 steps per BK=32
                unsigned a[2][4], b[4][2];
                const int ar = wm * 32 + (lane >> 2);
                const int j  = lane & 3;
                #pragma unroll
                for (int mt = 0; mt < 2; mt++) {
                    a[mt][0] = As[(ar + mt * 16) * 20 + s * 8 + j];
                    a[mt][1] = As[(ar + mt * 16 + 8) * 20 + s * 8 + j];
                    a[mt][2] = As[(ar + mt * 16) * 20 + s * 8 + j + 4];
                    a[mt][3] = As[(ar + mt * 16 + 8) * 20 + s * 8 + j + 4];
                }
                #pragma unroll
                for (int nt = 0; nt < 4; nt++) {
                    const int bn = wn * 32 + nt * 8 + (lane >> 2);
                    b[nt][0] = Bs[bn * 20 + s * 8 + j];
                    b[nt][1] = Bs[bn * 20 + s * 8 + j + 4];
                }
                #pragma unroll
                for (int mt = 0; mt < 2; mt++)
                    #pragma unroll
                    for (int nt = 0; nt < 4; nt++)
                        mma16(acc[mt][nt], a[mt], b[nt]);
            }
        }

        #pragma unroll
        for (int mt = 0; mt < 2; mt++) {
            long r0 = rowbase + wm * 32 + mt * 16 + (lane >> 2);
            #pragma unroll
            for (int nt = 0; nt < 4; nt++) {
                int cc = wn * 32 + nt * 8 + 2 * (lane & 3);
                *(float2*)(outp + r0 * 64 + cc)       = make_float2(acc[mt][nt][0], acc[mt][nt][1]);
                *(float2*)(outp + (r0 + 8) * 64 + cc) = make_float2(acc[mt][nt][2], acc[mt][nt][3]);
            }
        }
    } else {
        // ================= tf32 path (V) =================
        const float* W = Wv;
        unsigned* AsBase = qsm;                 // [2][128][36]
        unsigned* BsBase = qsm + 2 * 128 * 36;  // [2][32][72]

        const int ar_ = tid >> 3, ac4_ = tid & 7;
        const int br_ = tid >> 4, bc4_ = tid & 15;

        float4 ra[4], rb[2];
        #pragma unroll
        for (int i = 0; i < 4; i++)
            ra[i] = *(const float4*)(x + (rowbase + ar_ + i * 32) * 256 + ac4_ * 4);
        #pragma unroll
        for (int i = 0; i < 2; i++)
            rb[i] = *(const float4*)(W + (br_ + i * 16) * 64 + bc4_ * 4);

        for (int k0 = 0; k0 < 8; k0++) {
            const int buf = k0 & 1;
            unsigned* As = AsBase + buf * 128 * 36;
            unsigned* Bs = BsBase + buf * 32 * 72;

            #pragma unroll
            for (int i = 0; i < 4; i++) {
                unsigned* p = As + (ar_ + i * 32) * 36 + ac4_ * 4;
                p[0] = f2tf(ra[i].x); p[1] = f2tf(ra[i].y);
                p[2] = f2tf(ra[i].z); p[3] = f2tf(ra[i].w);
            }
            #pragma unroll
            for (int i = 0; i < 2; i++) {
                unsigned* p = Bs + (br_ + i * 16) * 72 + bc4_ * 4;
                p[0] = f2tf(rb[i].x); p[1] = f2tf(rb[i].y);
                p[2] = f2tf(rb[i].z); p[3] = f2tf(rb[i].w);
            }

            if (k0 < 7) {
                const int kn = (k0 + 1) * 32;
                #pragma unroll
                for (int i = 0; i < 4; i++)
                    ra[i] = *(const float4*)(x + (rowbase + ar_ + i * 32) * 256 + kn + ac4_ * 4);
                #pragma unroll
                for (int i = 0; i < 2; i++)
                    rb[i] = *(const float4*)(W + (kn + br_ + i * 16) * 64 + bc4_ * 4);
            }
            __syncthreads();

            #pragma unroll
            for (int kk = 0; kk < 4; kk++) {
                unsigned a[2][4], b[4][2];
                const int ar = wm * 32 + (lane >> 2);
                const int ac = kk * 8 + (lane & 3);
                #pragma unroll
                for (int mt = 0; mt < 2; mt++) {
                    a[mt][0] = As[(ar + mt * 16) * 36 + ac];
                    a[mt][1] = As[(ar + mt * 16 + 8) * 36 + ac];
                    a[mt][2] = As[(ar + mt * 16) * 36 + ac + 4];
                    a[mt][3] = As[(ar + mt * 16 + 8) * 36 + ac + 4];
                }
                const int bk = kk * 8 + (lane & 3);
                #pragma unroll
                for (int nt = 0; nt < 4; nt++) {
                    const int bn = wn * 32 + nt * 8 + (lane >> 2);
                    b[nt][0] = Bs[bk * 72 + bn];
                    b[nt][1] = Bs[(bk + 4) * 72 + bn];
                }
                #pragma unroll
                for (int mt = 0; mt < 2; mt++)
                    #pragma unroll
                    for (int nt = 0; nt < 4; nt++)
                        mma8(acc[mt][nt], a[mt], b[nt]);
            }
        }

        #pragma unroll
        for (int mt = 0; mt < 2; mt++) {
            long r0 = rowbase + wm * 32 + mt * 16 + (lane >> 2);
            #pragma unroll
            for (int nt = 0; nt < 4; nt++) {
                int cc = wn * 32 + nt * 8 + 2 * (lane & 3);
                *(float2*)(g_V + r0 * 64 + cc)       = make_float2(acc[mt][nt][0], acc[mt][nt][1]);
                *(float2*)(g_V + (r0 + 8) * 64 + cc) = make_float2(acc[mt][nt][2], acc[mt][nt][3]);
            }
        }
    }
}

// ---------------------------------------------------------------------------
// Kernel 2: fused causal attention, one CTA per batch, 2 CTAs/SM.
//  - QK^T in bf16 m16n8k16 (K packed bf16x2 in smem, 37 KB)
//  - P transformed C-frag -> A-frag via in-quad shuffles (no smem round-trip)
//  - P.V in tf32 (V tf32 in smem, pad 68)
//  - balanced causal schedule: warp w does 16-row tiles {w, 15-w} (9 units each)
// ---------------------------------------------------------------------------
#define KW_ 36   // words per K row: 32 bf16x2 + 4 pad  -> banks 4r+j, conflict-free
#define VW_ 68   // words per V row: 64 + 4 pad         -> banks 4j+r, conflict-free
#define ATTN_SMEM_BYTES ((256 * KW_ + 256 * VW_) * 4)

__global__ __launch_bounds__(256, 2) void attn_kernel(float* __restrict__ out)
{
    extern __shared__ unsigned sm[];
    unsigned* sK = sm;              // [256][KW_] bf16x2 words
    unsigned* sV = sm + 256 * KW_;  // [256][VW_] tf32 words

    const int tid  = threadIdx.x;
    const int lane = tid & 31;
    const int warp = tid >> 5;
    const int j    = lane & 3;
    const int qr   = lane >> 2;

    const int b = blockIdx.x;
    const float* Qg = g_Q + (long)b * T_ * H_;
    const float* Kg = g_K + (long)b * T_ * H_;
    const float* Vg = g_V + (long)b * T_ * H_;
    float* ob = out + (long)b * T_ * H_;

    // Stage K (bf16 packed) and V (tf32) into smem.
    #pragma unroll
    for (int i = 0; i < 16; i++) {
        int idx = tid + i * 256;
        int r = idx >> 4, c4 = idx & 15;
        float4 kv = *(const float4*)(Kg + r * 64 + c4 * 4);
        sK[r * KW_ + c4 * 2 + 0] = pkbf(kv.x, kv.y);
        sK[r * KW_ + c4 * 2 + 1] = pkbf(kv.z, kv.w);
        float4 vv = *(const float4*)(Vg + r * 64 + c4 * 4);
        sV[r * VW_ + c4 * 4 + 0] = f2tf(vv.x);
        sV[r * VW_ + c4 * 4 + 1] = f2tf(vv.y);
        sV[r * VW_ + c4 * 4 + 2] = f2tf(vv.z);
        sV[r * VW_ + c4 * 4 + 3] = f2tf(vv.w);
    }
    __syncthreads();

    #pragma unroll 1
    for (int half = 0; half < 2; half++) {
        const int m  = (half == 0) ? warp : 15 - warp;
        const int t0 = m * 16;

        // Q bf16 A-frags: 4 k16 steps over head dim 64.
        unsigned aq[4][4];
        {
            const int r = t0 + qr;
            #pragma unroll
            for (int st = 0; st < 4; st++) {
                const int c = st * 16 + 2 * j;
                aq[st][0] = pkbf(Qg[r * 64 + c],           Qg[r * 64 + c + 1]);
                aq[st][1] = pkbf(Qg[(r + 8) * 64 + c],     Qg[(r + 8) * 64 + c + 1]);
                aq[st][2] = pkbf(Qg[r * 64 + c + 8],       Qg[r * 64 + c + 9]);
                aq[st][3] = pkbf(Qg[(r + 8) * 64 + c + 8], Qg[(r + 8) * 64 + c + 9]);
            }
        }

        float o[8][4];
        #pragma unroll
        for (int nt = 0; nt < 8; nt++)
            #pragma unroll
            for (int c = 0; c < 4; c++) o[nt][c] = 0.f;
        float rs[2] = {0.f, 0.f};

        const int nb = m / 2 + 1;
        for (int sb = 0; sb < nb; sb++) {
            const int s0 = sb * 32;

            // --- S = Q @ K^T, 16x32 block, bf16 k16 ---
            float sacc[4][4];
            #pragma unroll
            for (int nt = 0; nt < 4; nt++)
                #pragma unroll
                for (int c = 0; c < 4; c++) sacc[nt][c] = 0.f;

            #pragma unroll
            for (int st = 0; st < 4; st++) {
                unsigned bk[4][2];
                #pragma unroll
                for (int nt = 0; nt < 4; nt++) {
                    int ss = s0 + nt * 8 + qr;
                    bk[nt][0] = sK[ss * KW_ + st * 8 + j];
                    bk[nt][1] = sK[ss * KW_ + st * 8 + j + 4];
                }
                #pragma unroll
                for (int nt = 0; nt < 4; nt++)
                    mma16(sacc[nt], aq[st], bk[nt]);
            }

            // --- mask + exp + denom + C->A frag transform via quad shuffles ---
            unsigned ap[4][4];
            const int tlo = t0 + qr, thi = tlo + 8;
            const int srcA = (lane & ~3) | (j >> 1);
            const int srcB = srcA + 2;
            const bool odd = (j & 1);
            #pragma unroll
            for (int nt = 0; nt < 4; nt++) {
                const int clo = s0 + nt * 8 + 2 * j;
                float pe0 = (clo     <= tlo) ? __expf(sacc[nt][0] * 0.0625f) : 0.f;
                float pe1 = (clo + 1 <= tlo) ? __expf(sacc[nt][1] * 0.0625f) : 0.f;
                float pe2 = (clo     <= thi) ? __expf(sacc[nt][2] * 0.0625f) : 0.f;
                float pe3 = (clo + 1 <= thi) ? __expf(sacc[nt][3] * 0.0625f) : 0.f;
                rs[0] += pe0 + pe1;
                rs[1] += pe2 + pe3;
                // P[row][col]: col c held by lane (c>>1) slot (c&1). A-frag needs
                // cols {j, j+4} at rows {r, r+8}.
                float g0 = __shfl_sync(0xffffffffu, pe0, srcA);
                float g1 = __shfl_sync(0xffffffffu, pe1, srcA);
                float h0 = __shfl_sync(0xffffffffu, pe0, srcB);
                float h1 = __shfl_sync(0xffffffffu, pe1, srcB);
                float g2 = __shfl_sync(0xffffffffu, pe2, srcA);
                float g3 = __shfl_sync(0xffffffffu, pe3, srcA);
                float h2 = __shfl_sync(0xffffffffu, pe2, srcB);
                float h3 = __shfl_sync(0xffffffffu, pe3, srcB);
                ap[nt][0] = f2tf(odd ? g1 : g0);  // P[r][j]
                ap[nt][1] = f2tf(odd ? g3 : g2);  // P[r+8][j]
                ap[nt][2] = f2tf(odd ? h1 : h0);  // P[r][j+4]
                ap[nt][3] = f2tf(odd ? h3 : h2);  // P[r+8][j+4]
            }

            // --- O += P @ V, tf32 k8; k-chunk kt uses ap[kt] ---
            #pragma unroll
            for (int kt = 0; kt < 4; kt++) {
                unsigned bv[8][2];
                const int sv = s0 + kt * 8 + j;
                #pragma unroll
                for (int nt = 0; nt < 8; nt++) {
                    const int hh = nt * 8 + qr;
                    bv[nt][0] = sV[sv * VW_ + hh];
                    bv[nt][1] = sV[(sv + 4) * VW_ + hh];
                }
                #pragma unroll
                for (int nt = 0; nt < 8; nt++)
                    mma8(o[nt], ap[kt], bv[nt]);
            }
        }

        // Denominators: reduce across the 4 lanes of each row-quad.
        #pragma unroll
        for (int h2 = 0; h2 < 2; h2++) {
            float r = rs[h2];
            r += __shfl_xor_sync(0xffffffffu, r, 1);
            r += __shfl_xor_sync(0xffffffffu, r, 2);
            rs[h2] = 1.f / r;
        }

        // Write this tile's output.
        const int r = t0 + qr;
        #pragma unroll
        for (int nt = 0; nt < 8; nt++) {
            const int cc = nt * 8 + 2 * j;
            *(float2*)(ob + r * 64 + cc) =
                make_float2(o[nt][0] * rs[0], o[nt][1] * rs[0]);
            *(float2*)(ob + (r + 8) * 64 + cc) =
                make_float2(o[nt][2] * rs[1], o[nt][3] * rs[1]);
        }
    }
}

// ---------------------------------------------------------------------------
extern "C" void kernel_launch(void* const* d_in, const int* in_sizes, int n_in,
                              void* d_out, int out_size)
{
    const float* x  = (const float*)d_in[0];
    const float* Wq = (const float*)d_in[1];
    const float* Wk = (const float*)d_in[2];
    const float* Wv = (const float*)d_in[3];
    float* out = (float*)d_out;

    (void)in_sizes; (void)n_in; (void)out_size;

    cudaFuncSetAttribute(qkv_kernel, cudaFuncAttributeMaxDynamicSharedMemorySize,
                         QKV_SMEM_BYTES);
    cudaFuncSetAttribute(attn_kernel, cudaFuncAttributeMaxDynamicSharedMemorySize,
                         ATTN_SMEM_BYTES);

    qkv_kernel<<<dim3(3, (B_ * T_) / 128), 256, QKV_SMEM_BYTES>>>(x, Wq, Wk, Wv);
    attn_kernel<<<B_, 256, ATTN_SMEM_BYTES>>>(out);
}

// round 5
// speedup vs baseline: 1.3337x; 1.0324x over previous
#include <cuda_runtime.h>
#include <cstdint>

#define B_  512
#define T_  256
#define C_  256
#define H_  64

// Scratch for Q, K, V projections (allocation-free: __device__ globals).
__device__ float g_Q[B_ * T_ * H_];
__device__ float g_K[B_ * T_ * H_];
__device__ float g_V[B_ * T_ * H_];

// fp32 -> tf32 bits, round-to-nearest (unbiased; load-bearing for precision).
__device__ __forceinline__ unsigned f2tf(float x) {
    unsigned r;
    asm("cvt.rna.tf32.f32 %0, %1;" : "=r"(r) : "f"(x));
    return r;
}
// pack two fp32 -> bf16x2 word {lo, hi} (lo = first/even-k element).
__device__ __forceinline__ unsigned pkbf(float lo, float hi) {
    unsigned r;
    asm("cvt.rn.bf16x2.f32 %0, %1, %2;" : "=r"(r) : "f"(hi), "f"(lo));
    return r;
}

// m16n8k8 tf32 mma: D += A*B.
__device__ __forceinline__ void mma8(float* d, const unsigned* a, const unsigned* b) {
    asm volatile(
        "mma.sync.aligned.m16n8k8.row.col.f32.tf32.tf32.f32 "
        "{%0,%1,%2,%3},{%4,%5,%6,%7},{%8,%9},{%0,%1,%2,%3};"
        : "+f"(d[0]), "+f"(d[1]), "+f"(d[2]), "+f"(d[3])
        : "r"(a[0]), "r"(a[1]), "r"(a[2]), "r"(a[3]), "r"(b[0]), "r"(b[1]));
}
// m16n8k16 bf16 mma: D += A*B.
__device__ __forceinline__ void mma16(float* d, const unsigned* a, const unsigned* b) {
    asm volatile(
        "mma.sync.aligned.m16n8k16.row.col.f32.bf16.bf16.f32 "
        "{%0,%1,%2,%3},{%4,%5,%6,%7},{%8,%9},{%0,%1,%2,%3};"
        : "+f"(d[0]), "+f"(d[1]), "+f"(d[2]), "+f"(d[3])
        : "r"(a[0]), "r"(a[1]), "r"(a[2]), "r"(a[3]), "r"(b[0]), "r"(b[1]));
}
// ldmatrix x4: four 8x8 b16 tiles; per-lane shared address (lane i -> row of tile i>>3).
__device__ __forceinline__ void ldsm4(unsigned& r0, unsigned& r1, unsigned& r2, unsigned& r3,
                                      unsigned saddr) {
    asm volatile("ldmatrix.sync.aligned.m8n8.x4.shared.b16 {%0,%1,%2,%3}, [%4];"
                 : "=r"(r0), "=r"(r1), "=r"(r2), "=r"(r3) : "r"(saddr));
}
__device__ __forceinline__ unsigned scvta(const void* p) {
    return (unsigned)__cvta_generic_to_shared(p);
}

// ---------------------------------------------------------------------------
// Kernel 1: QKV projection, mixed precision.
//   which 0/1 (Q,K): bf16 m16n8k16, fragments via ldmatrix.x4 (8x fewer L1 ops)
//   which 2   (V)  : tf32 m16n8k8 (V errors propagate 1:1 to output)
// CTA tile 128x64, BK=32, 8 warps (4x2), double-buffered smem, 1 barrier/step.
// grid=(3, nblocks): g-variants of an m-block adjacent -> x tile reused in L2.
// ---------------------------------------------------------------------------
#define QKV_SMEM_WORDS (2 * 128 * 36 + 2 * 32 * 72)
#define QKV_SMEM_BYTES (QKV_SMEM_WORDS * 4)

__global__ __launch_bounds__(256, 2) void qkv_kernel(
    const float* __restrict__ x,
    const float* __restrict__ Wq,
    const float* __restrict__ Wk,
    const float* __restrict__ Wv)
{
    extern __shared__ unsigned qsm[];

    const int tid  = threadIdx.x;
    const int lane = tid & 31;
    const int warp = tid >> 5;
    const int wm   = warp >> 1;
    const int wn   = warp & 1;
    const int mblk = blockIdx.y;
    const int which = blockIdx.x;
    const long rowbase = (long)mblk * 128;

    float acc[2][4][4];
    #pragma unroll
    for (int i = 0; i < 2; i++)
        #pragma unroll
        for (int j = 0; j < 4; j++)
            #pragma unroll
            for (int c = 0; c < 4; c++) acc[i][j][c] = 0.f;

    if (which < 2) {
        // ================= bf16 path (Q, K) =================
        const float* W    = (which == 0) ? Wq : Wk;
        float*       outp = (which == 0) ? g_Q : g_K;
        unsigned* Aw = qsm;                 // [2][128][20] bf16x2 words
        unsigned* Bw = qsm + 2 * 128 * 20;  // [2][64][20]  bf16x2 words (n-major)
        const unsigned sA = scvta(Aw), sB = scvta(Bw);

        const int ar_ = tid >> 3, ac4_ = tid & 7;   // A: 128 rows x 8 float4
        const int n_  = tid & 63, g_   = tid >> 6;  // B: 64 n x 4 kw-groups

        // ldmatrix per-lane row selectors (tile = lane>>3).
        const int lrow  = (lane & 7) + ((lane >> 3) & 1) * 8;  // row within 16-row group
        const int lhalf = (lane >> 4) & 1;                     // 16B k-half (A) / nt-sel (B)
        // A tiles: (m-low,k-low),(m-high,k-low),(m-low,k-high),(m-high,k-high)
        //   row = base_m + lrow' where lrow' uses (lane>>3)&1; khalf = lane>>4.
        const int aRow  = (lane & 7) + ((lane >> 3) & 1) * 8;
        const int aHalf = (lane >> 4) & 1;
        // B tiles: (nt0,k-low),(nt0,k-high),(nt1,k-low),(nt1,k-high)
        const int bRow  = (lane & 7) + ((lane >> 4) & 1) * 8;  // within nt-pair's 16 rows
        const int bHalf = (lane >> 3) & 1;
        (void)lrow; (void)lhalf;

        float4 ra[4];
        float rbl[4], rbh[4];
        #pragma unroll
        for (int i = 0; i < 4; i++)
            ra[i] = *(const float4*)(x + (rowbase + ar_ + i * 32) * 256 + ac4_ * 4);
        #pragma unroll
        for (int i = 0; i < 4; i++) {
            int k = 2 * (g_ * 4 + i);
            rbl[i] = W[k * 64 + n_];
            rbh[i] = W[(k + 1) * 64 + n_];
        }

        for (int k0 = 0; k0 < 8; k0++) {
            const int buf = k0 & 1;
            unsigned* As = Aw + buf * 128 * 20;
            unsigned* Bs = Bw + buf * 64 * 20;

            #pragma unroll
            for (int i = 0; i < 4; i++) {
                unsigned* p = As + (ar_ + i * 32) * 20 + ac4_ * 2;
                p[0] = pkbf(ra[i].x, ra[i].y);
                p[1] = pkbf(ra[i].z, ra[i].w);
            }
            #pragma unroll
            for (int i = 0; i < 4; i++)
                Bs[n_ * 20 + g_ * 4 + i] = pkbf(rbl[i], rbh[i]);

            if (k0 < 7) {
                const int kn = (k0 + 1) * 32;
                #pragma unroll
                for (int i = 0; i < 4; i++)
                    ra[i] = *(const float4*)(x + (rowbase + ar_ + i * 32) * 256 + kn + ac4_ * 4);
                #pragma unroll
                for (int i = 0; i < 4; i++) {
                    int k = kn + 2 * (g_ * 4 + i);
                    rbl[i] = W[k * 64 + n_];
                    rbh[i] = W[(k + 1) * 64 + n_];
                }
            }
            __syncthreads();

            const unsigned aBufB = sA + buf * 128 * 20 * 4;
            const unsigned bBufB = sB + buf * 64 * 20 * 4;

            #pragma unroll
            for (int s = 0; s < 2; s++) {  // two k16 steps per BK=32
                unsigned a[2][4], b[4][2];
                #pragma unroll
                for (int mt = 0; mt < 2; mt++) {
                    unsigned addr = aBufB +
                        ((wm * 32 + mt * 16 + aRow) * 20 + s * 8 + aHalf * 4) * 4;
                    ldsm4(a[mt][0], a[mt][1], a[mt][2], a[mt][3], addr);
                }
                #pragma unroll
                for (int p = 0; p < 2; p++) {  // nt pairs (0,1) and (2,3)
                    unsigned addr = bBufB +
                        ((wn * 32 + p * 16 + bRow) * 20 + s * 8 + bHalf * 4) * 4;
                    ldsm4(b[2 * p][0], b[2 * p][1], b[2 * p + 1][0], b[2 * p + 1][1], addr);
                }
                #pragma unroll
                for (int mt = 0; mt < 2; mt++)
                    #pragma unroll
                    for (int nt = 0; nt < 4; nt++)
                        mma16(acc[mt][nt], a[mt], b[nt]);
            }
        }

        #pragma unroll
        for (int mt = 0; mt < 2; mt++) {
            long r0 = rowbase + wm * 32 + mt * 16 + (lane >> 2);
            #pragma unroll
            for (int nt = 0; nt < 4; nt++) {
                int cc = wn * 32 + nt * 8 + 2 * (lane & 3);
                *(float2*)(outp + r0 * 64 + cc)       = make_float2(acc[mt][nt][0], acc[mt][nt][1]);
                *(float2*)(outp + (r0 + 8) * 64 + cc) = make_float2(acc[mt][nt][2], acc[mt][nt][3]);
            }
        }
    } else {
        // ================= tf32 path (V) =================
        const float* W = Wv;
        unsigned* AsBase = qsm;                 // [2][128][36]
        unsigned* BsBase = qsm + 2 * 128 * 36;  // [2][32][72]

        const int ar_ = tid >> 3, ac4_ = tid & 7;
        const int br_ = tid >> 4, bc4_ = tid & 15;

        float4 ra[4], rb[2];
        #pragma unroll
        for (int i = 0; i < 4; i++)
            ra[i] = *(const float4*)(x + (rowbase + ar_ + i * 32) * 256 + ac4_ * 4);
        #pragma unroll
        for (int i = 0; i < 2; i++)
            rb[i] = *(const float4*)(W + (br_ + i * 16) * 64 + bc4_ * 4);

        for (int k0 = 0; k0 < 8; k0++) {
            const int buf = k0 & 1;
            unsigned* As = AsBase + buf * 128 * 36;
            unsigned* Bs = BsBase + buf * 32 * 72;

            #pragma unroll
            for (int i = 0; i < 4; i++) {
                unsigned* p = As + (ar_ + i * 32) * 36 + ac4_ * 4;
                p[0] = f2tf(ra[i].x); p[1] = f2tf(ra[i].y);
                p[2] = f2tf(ra[i].z); p[3] = f2tf(ra[i].w);
            }
            #pragma unroll
            for (int i = 0; i < 2; i++) {
                unsigned* p = Bs + (br_ + i * 16) * 72 + bc4_ * 4;
                p[0] = f2tf(rb[i].x); p[1] = f2tf(rb[i].y);
                p[2] = f2tf(rb[i].z); p[3] = f2tf(rb[i].w);
            }

            if (k0 < 7) {
                const int kn = (k0 + 1) * 32;
                #pragma unroll
                for (int i = 0; i < 4; i++)
                    ra[i] = *(const float4*)(x + (rowbase + ar_ + i * 32) * 256 + kn + ac4_ * 4);
                #pragma unroll
                for (int i = 0; i < 2; i++)
                    rb[i] = *(const float4*)(W + (kn + br_ + i * 16) * 64 + bc4_ * 4);
            }
            __syncthreads();

            #pragma unroll
            for (int kk = 0; kk < 4; kk++) {
                unsigned a[2][4], b[4][2];
                const int ar = wm * 32 + (lane >> 2);
                const int ac = kk * 8 + (lane & 3);
                #pragma unroll
                for (int mt = 0; mt < 2; mt++) {
                    a[mt][0] = As[(ar + mt * 16) * 36 + ac];
                    a[mt][1] = As[(ar + mt * 16 + 8) * 36 + ac];
                    a[mt][2] = As[(ar + mt * 16) * 36 + ac + 4];
                    a[mt][3] = As[(ar + mt * 16 + 8) * 36 + ac + 4];
                }
                const int bk = kk * 8 + (lane & 3);
                #pragma unroll
                for (int nt = 0; nt < 4; nt++) {
                    const int bn = wn * 32 + nt * 8 + (lane >> 2);
                    b[nt][0] = Bs[bk * 72 + bn];
                    b[nt][1] = Bs[(bk + 4) * 72 + bn];
                }
                #pragma unroll
                for (int mt = 0; mt < 2; mt++)
                    #pragma unroll
                    for (int nt = 0; nt < 4; nt++)
                        mma8(acc[mt][nt], a[mt], b[nt]);
            }
        }

        #pragma unroll
        for (int mt = 0; mt < 2; mt++) {
            long r0 = rowbase + wm * 32 + mt * 16 + (lane >> 2);
            #pragma unroll
            for (int nt = 0; nt < 4; nt++) {
                int cc = wn * 32 + nt * 8 + 2 * (lane & 3);
                *(float2*)(g_V + r0 * 64 + cc)       = make_float2(acc[mt][nt][0], acc[mt][nt][1]);
                *(float2*)(g_V + (r0 + 8) * 64 + cc) = make_float2(acc[mt][nt][2], acc[mt][nt][3]);
            }
        }
    }
}

// ---------------------------------------------------------------------------
// Kernel 2: fused causal attention, one CTA per batch, 2 CTAs/SM.
//  - QK^T bf16 m16n8k16; K frags via ldmatrix.x4 (rows stride 36 words: banks
//    4r -> conflict-free)
//  - V pad 72 words/row: V-frag bank index = 8j+qr, a perfect 32-bank
//    permutation (68 in R4 was 4j+qr -> 2-way conflicts; restored)
//  - P C-frag -> A-frag via in-quad shuffles (no smem round-trip)
//  - balanced causal schedule: warp w does 16-row tiles {w, 15-w}
// ---------------------------------------------------------------------------
#define KW_ 36   // words per K row: 32 bf16x2 + 4 pad
#define VW_ 72   // words per V row: 64 tf32 + 8 pad
#define ATTN_SMEM_BYTES ((256 * KW_ + 256 * VW_) * 4)

__global__ __launch_bounds__(256, 2) void attn_kernel(float* __restrict__ out)
{
    extern __shared__ unsigned sm[];
    unsigned* sK = sm;              // [256][KW_] bf16x2 words
    unsigned* sV = sm + 256 * KW_;  // [256][VW_] tf32 words
    const unsigned sKb = scvta(sK);

    const int tid  = threadIdx.x;
    const int lane = tid & 31;
    const int warp = tid >> 5;
    const int j    = lane & 3;
    const int qr   = lane >> 2;

    // ldmatrix B-pattern lane selectors for K frags.
    const int bRow  = (lane & 7) + ((lane >> 4) & 1) * 8;  // row within nt-pair
    const int bHalf = (lane >> 3) & 1;                     // k 16B half

    const int b = blockIdx.x;
    const float* Qg = g_Q + (long)b * T_ * H_;
    const float* Kg = g_K + (long)b * T_ * H_;
    const float* Vg = g_V + (long)b * T_ * H_;
    float* ob = out + (long)b * T_ * H_;

    // Stage K (bf16 packed) and V (tf32) into smem.
    #pragma unroll
    for (int i = 0; i < 16; i++) {
        int idx = tid + i * 256;
        int r = idx >> 4, c4 = idx & 15;
        float4 kv = *(const float4*)(Kg + r * 64 + c4 * 4);
        sK[r * KW_ + c4 * 2 + 0] = pkbf(kv.x, kv.y);
        sK[r * KW_ + c4 * 2 + 1] = pkbf(kv.z, kv.w);
        float4 vv = *(const float4*)(Vg + r * 64 + c4 * 4);
        sV[r * VW_ + c4 * 4 + 0] = f2tf(vv.x);
        sV[r * VW_ + c4 * 4 + 1] = f2tf(vv.y);
        sV[r * VW_ + c4 * 4 + 2] = f2tf(vv.z);
        sV[r * VW_ + c4 * 4 + 3] = f2tf(vv.w);
    }
    __syncthreads();

    #pragma unroll 1
    for (int half = 0; half < 2; half++) {
        const int m  = (half == 0) ? warp : 15 - warp;
        const int t0 = m * 16;

        // Q bf16 A-frags: 4 k16 steps over head dim 64.
        unsigned aq[4][4];
        {
            const int r = t0 + qr;
            #pragma unroll
            for (int st = 0; st < 4; st++) {
                const int c = st * 16 + 2 * j;
                aq[st][0] = pkbf(Qg[r * 64 + c],           Qg[r * 64 + c + 1]);
                aq[st][1] = pkbf(Qg[(r + 8) * 64 + c],     Qg[(r + 8) * 64 + c + 1]);
                aq[st][2] = pkbf(Qg[r * 64 + c + 8],       Qg[r * 64 + c + 9]);
                aq[st][3] = pkbf(Qg[(r + 8) * 64 + c + 8], Qg[(r + 8) * 64 + c + 9]);
            }
        }

        float o[8][4];
        #pragma unroll
        for (int nt = 0; nt < 8; nt++)
            #pragma unroll
            for (int c = 0; c < 4; c++) o[nt][c] = 0.f;
        float rs[2] = {0.f, 0.f};

        const int nb = m / 2 + 1;
        for (int sb = 0; sb < nb; sb++) {
            const int s0 = sb * 32;

            // --- S = Q @ K^T, 16x32 block, bf16 k16, K frags via ldmatrix ---
            float sacc[4][4];
            #pragma unroll
            for (int nt = 0; nt < 4; nt++)
                #pragma unroll
                for (int c = 0; c < 4; c++) sacc[nt][c] = 0.f;

            #pragma unroll
            for (int st = 0; st < 4; st++) {
                unsigned bk[4][2];
                #pragma unroll
                for (int p = 0; p < 2; p++) {
                    unsigned addr = sKb +
                        ((s0 + p * 16 + bRow) * KW_ + st * 8 + bHalf * 4) * 4;
                    ldsm4(bk[2 * p][0], bk[2 * p][1], bk[2 * p + 1][0], bk[2 * p + 1][1], addr);
                }
                #pragma unroll
                for (int nt = 0; nt < 4; nt++)
                    mma16(sacc[nt], aq[st], bk[nt]);
            }

            // --- mask + exp + denom + C->A frag transform via quad shuffles ---
            unsigned ap[4][4];
            const int tlo = t0 + qr, thi = tlo + 8;
            const int srcA = (lane & ~3) | (j >> 1);
            const int srcB = srcA + 2;
            const bool odd = (j & 1);
            #pragma unroll
            for (int nt = 0; nt < 4; nt++) {
                const int clo = s0 + nt * 8 + 2 * j;
                float pe0 = (clo     <= tlo) ? __expf(sacc[nt][0] * 0.0625f) : 0.f;
                float pe1 = (clo + 1 <= tlo) ? __expf(sacc[nt][1] * 0.0625f) : 0.f;
                float pe2 = (clo     <= thi) ? __expf(sacc[nt][2] * 0.0625f) : 0.f;
                float pe3 = (clo + 1 <= thi) ? __expf(sacc[nt][3] * 0.0625f) : 0.f;
                rs[0] += pe0 + pe1;
                rs[1] += pe2 + pe3;
                float g0 = __shfl_sync(0xffffffffu, pe0, srcA);
                float g1 = __shfl_sync(0xffffffffu, pe1, srcA);
                float h0 = __shfl_sync(0xffffffffu, pe0, srcB);
                float h1 = __shfl_sync(0xffffffffu, pe1, srcB);
                float g2 = __shfl_sync(0xffffffffu, pe2, srcA);
                float g3 = __shfl_sync(0xffffffffu, pe3, srcA);
                float h2 = __shfl_sync(0xffffffffu, pe2, srcB);
                float h3 = __shfl_sync(0xffffffffu, pe3, srcB);
                ap[nt][0] = f2tf(odd ? g1 : g0);  // P[r][j]
                ap[nt][1] = f2tf(odd ? g3 : g2);  // P[r+8][j]
                ap[nt][2] = f2tf(odd ? h1 : h0);  // P[r][j+4]
                ap[nt][3] = f2tf(odd ? h3 : h2);  // P[r+8][j+4]
            }

            // --- O += P @ V, tf32 k8; k-chunk kt uses ap[kt] ---
            #pragma unroll
            for (int kt = 0; kt < 4; kt++) {
                unsigned bv[8][2];
                const int sv = s0 + kt * 8 + j;
                #pragma unroll
                for (int nt = 0; nt < 8; nt++) {
                    const int hh = nt * 8 + qr;
                    bv[nt][0] = sV[sv * VW_ + hh];
                    bv[nt][1] = sV[(sv + 4) * VW_ + hh];
                }
                #pragma unroll
                for (int nt = 0; nt < 8; nt++)
                    mma8(o[nt], ap[kt], bv[nt]);
            }
        }

        // Denominators: reduce across the 4 lanes of each row-quad.
        #pragma unroll
        for (int h2 = 0; h2 < 2; h2++) {
            float r = rs[h2];
            r += __shfl_xor_sync(0xffffffffu, r, 1);
            r += __shfl_xor_sync(0xffffffffu, r, 2);
            rs[h2] = 1.f / r;
        }

        // Write this tile's output.
        const int r = t0 + qr;
        #pragma unroll
        for (int nt = 0; nt < 8; nt++) {
            const int cc = nt * 8 + 2 * j;
            *(float2*)(ob + r * 64 + cc) =
                make_float2(o[nt][0] * rs[0], o[nt][1] * rs[0]);
            *(float2*)(ob + (r + 8) * 64 + cc) =
                make_float2(o[nt][2] * rs[1], o[nt][3] * rs[1]);
        }
    }
}

// ---------------------------------------------------------------------------
extern "C" void kernel_launch(void* const* d_in, const int* in_sizes, int n_in,
                              void* d_out, int out_size)
{
    const float* x  = (const float*)d_in[0];
    const float* Wq = (const float*)d_in[1];
    const float* Wk = (const float*)d_in[2];
    const float* Wv = (const float*)d_in[3];
    float* out = (float*)d_out;

    (void)in_sizes; (void)n_in; (void)out_size;

    cudaFuncSetAttribute(qkv_kernel, cudaFuncAttributeMaxDynamicSharedMemorySize,
                         QKV_SMEM_BYTES);
    cudaFuncSetAttribute(attn_kernel, cudaFuncAttributeMaxDynamicSharedMemorySize,
                         ATTN_SMEM_BYTES);

    qkv_kernel<<<dim3(3, (B_ * T_) / 128), 256, QKV_SMEM_BYTES>>>(x, Wq, Wk, Wv);
    attn_kernel<<<B_, 256, ATTN_SMEM_BYTES>>>(out);
}